// round 5
// baseline (speedup 1.0000x reference)
#include <cuda_runtime.h>

#define N_NODES 100000
#define DIN     128
#define HDIM    64

// Scratch (device globals; zero at module load, k_out re-zeroes g_deg each run)
__device__ float g_deg[N_NODES];   // edge-only degree (self-loop +1 added at use)
__device__ float g_dis[N_NODES];
__device__ float g_p[N_NODES];     // dis[i] * val[i]  (current layer)
__device__ float g_acc[N_NODES];   // accumulator, init = p (self-loop folded)
__device__ __align__(16) float g_w[DIN];
__device__ float g_c1;
__device__ float g_c2;

__device__ __forceinline__ int4 ldcs4i(const int* p) {
    return __ldcs((const int4*)p);
}
__device__ __forceinline__ float4 ldcs4f(const float* p) {
    return __ldcs((const float4*)p);
}

// ---------------------------------------------------------------------------
// K0: weight collapse only (1 block).
//   u = W2 @ fc_w (64), w = W1 @ u (128), c1 = b1.u, c2 = b2.fc_w + fc_b
// ---------------------------------------------------------------------------
__global__ void k_init(const float* __restrict__ W1, const float* __restrict__ b1,
                       const float* __restrict__ W2, const float* __restrict__ b2,
                       const float* __restrict__ fc_w, const float* __restrict__ fc_b) {
    __shared__ float u[HDIM];
    int t = threadIdx.x;
    if (t < HDIM) {
        float acc = 0.f;
        #pragma unroll 8
        for (int j = 0; j < HDIM; ++j) acc += W2[t * HDIM + j] * fc_w[j];
        u[t] = acc;
    }
    __syncthreads();
    if (t < DIN) {
        float acc = 0.f;
        #pragma unroll 8
        for (int j = 0; j < HDIM; ++j) acc += W1[t * HDIM + j] * u[j];
        g_w[t] = acc;
    }
    if (t == 0) {
        float c1 = 0.f, c2 = 0.f;
        for (int j = 0; j < HDIM; ++j) { c1 += b1[j] * u[j]; c2 += b2[j] * fc_w[j]; }
        g_c1 = c1;
        g_c2 = c2 + fc_b[0];
    }
}

// ---------------------------------------------------------------------------
// K1: deg[dst] += ew   -- 8 edges per thread.
// ---------------------------------------------------------------------------
__global__ void k_deg_acc(const int* __restrict__ dst,
                          const float* __restrict__ ew, int E) {
    int e8 = (blockIdx.x * blockDim.x + threadIdx.x) * 8;
    if (e8 + 7 < E) {
        int4   d0 = ldcs4i(dst + e8);
        int4   d1 = ldcs4i(dst + e8 + 4);
        float4 w0 = ldcs4f(ew + e8);
        float4 w1 = ldcs4f(ew + e8 + 4);
        atomicAdd(&g_deg[d0.x], w0.x);
        atomicAdd(&g_deg[d0.y], w0.y);
        atomicAdd(&g_deg[d0.z], w0.z);
        atomicAdd(&g_deg[d0.w], w0.w);
        atomicAdd(&g_deg[d1.x], w1.x);
        atomicAdd(&g_deg[d1.y], w1.y);
        atomicAdd(&g_deg[d1.z], w1.z);
        atomicAdd(&g_deg[d1.w], w1.w);
    } else {
        for (int e = e8; e < E; ++e)
            atomicAdd(&g_deg[dst[e]], ew[e]);
    }
}

// ---------------------------------------------------------------------------
// K2: per node -- dis = rsqrt(1+deg); s = x.w; p = dis*s; acc = p (self-loop)
// One warp processes 8 nodes (MLP=8 on the x stream).
// ---------------------------------------------------------------------------
__global__ void k_node(const float* __restrict__ x, int n) {
    int warp = (blockIdx.x * blockDim.x + threadIdx.x) >> 5;
    int lane = threadIdx.x & 31;
    int base = warp * 8;
    if (base >= n) return;

    float4 wv = ((const float4*)g_w)[lane];

    float acc[8];
    if (base + 7 < n) {
        const float4* xr = (const float4*)(x + (size_t)base * DIN);
        #pragma unroll
        for (int k = 0; k < 8; ++k) {
            float4 v = xr[k * 32 + lane];
            acc[k] = v.x * wv.x + v.y * wv.y + v.z * wv.z + v.w * wv.w;
        }
    } else {
        #pragma unroll
        for (int k = 0; k < 8; ++k) {
            if (base + k < n) {
                const float4* xr = (const float4*)(x + (size_t)(base + k) * DIN);
                float4 v = xr[lane];
                acc[k] = v.x * wv.x + v.y * wv.y + v.z * wv.z + v.w * wv.w;
            } else {
                acc[k] = 0.f;
            }
        }
    }

    #pragma unroll
    for (int o = 16; o; o >>= 1) {
        #pragma unroll
        for (int k = 0; k < 8; ++k)
            acc[k] += __shfl_xor_sync(0xFFFFFFFFu, acc[k], o);
    }

    if (lane < 8 && base + lane < n) {
        int node = base + lane;
        float s = acc[lane];
        float deg = g_deg[node] + 1.0f;            // + self-loop
        float dis = rsqrtf(fmaxf(deg, 1e-12f));    // deg >= 1 always
        float p = dis * s;
        g_dis[node] = dis;
        g_p[node]   = p;
        g_acc[node] = p;     // self-loop term dis^2*s; outer dis applied later
    }
}

// ---------------------------------------------------------------------------
// K prop (both layers): acc[dst] += ew * p[src].  8 edges per thread.
// ---------------------------------------------------------------------------
__global__ void k_prop(const int* __restrict__ ei,
                       const float* __restrict__ ew, int E) {
    int e8 = (blockIdx.x * blockDim.x + threadIdx.x) * 8;
    if (e8 + 7 < E) {
        int4   s0 = ldcs4i(ei + e8);
        int4   s1 = ldcs4i(ei + e8 + 4);
        int4   d0 = ldcs4i(ei + (size_t)E + e8);
        int4   d1 = ldcs4i(ei + (size_t)E + e8 + 4);
        float4 w0 = ldcs4f(ew + e8);
        float4 w1 = ldcs4f(ew + e8 + 4);
        // issue all 8 gathers before any atomic
        float p0 = g_p[s0.x], p1 = g_p[s0.y], p2 = g_p[s0.z], p3 = g_p[s0.w];
        float p4 = g_p[s1.x], p5 = g_p[s1.y], p6 = g_p[s1.z], p7 = g_p[s1.w];
        atomicAdd(&g_acc[d0.x], w0.x * p0);
        atomicAdd(&g_acc[d0.y], w0.y * p1);
        atomicAdd(&g_acc[d0.z], w0.z * p2);
        atomicAdd(&g_acc[d0.w], w0.w * p3);
        atomicAdd(&g_acc[d1.x], w1.x * p4);
        atomicAdd(&g_acc[d1.y], w1.y * p5);
        atomicAdd(&g_acc[d1.z], w1.z * p6);
        atomicAdd(&g_acc[d1.w], w1.w * p7);
    } else {
        for (int e = e8; e < E; ++e)
            atomicAdd(&g_acc[ei[(size_t)E + e]], ew[e] * g_p[ei[e]]);
    }
}

// ---------------------------------------------------------------------------
// K mid: t = c1 + dis*acc;  p2 = dis*t;  acc = p2 (self-loop of layer 2)
// ---------------------------------------------------------------------------
__global__ void k_mid(int n) {
    int i = blockIdx.x * blockDim.x + threadIdx.x;
    if (i < n) {
        float dis = g_dis[i];
        float t   = fmaf(dis, g_acc[i], g_c1);
        float p2  = dis * t;
        g_p[i]   = p2;
        g_acc[i] = p2;
    }
}

// K out: out = rint(clip(c2 + dis*acc, 0, 10)); also re-zero g_deg for replay.
__global__ void k_out(float* __restrict__ out, int n) {
    int i = blockIdx.x * blockDim.x + threadIdx.x;
    if (i < n) {
        float v = fmaf(g_dis[i], g_acc[i], g_c2);
        out[i] = rintf(fminf(fmaxf(v, 0.f), 10.f));
        g_deg[i] = 0.0f;        // leave buffer zeroed for the next invocation
    }
}

extern "C" void kernel_launch(void* const* d_in, const int* in_sizes, int n_in,
                              void* d_out, int out_size) {
    const float* x    = (const float*)d_in[0];
    const int*   ei   = (const int*)d_in[1];    // int32 [2, E]
    const float* ew   = (const float*)d_in[2];
    const float* W1   = (const float*)d_in[3];
    const float* b1   = (const float*)d_in[4];
    const float* W2   = (const float*)d_in[5];
    const float* b2   = (const float*)d_in[6];
    const float* fc_w = (const float*)d_in[7];
    const float* fc_b = (const float*)d_in[8];
    float*       out  = (float*)d_out;

    const int E = in_sizes[2];             // 1600000
    const int N = in_sizes[0] / DIN;       // 100000

    const int TB = 256;
    const int nb_nodes  = (N + TB - 1) / TB;
    const int nb_edges8 = ((E + 7) / 8 + TB - 1) / TB;
    const int nb_warps  = (((N + 7) / 8) * 32 + TB - 1) / TB;  // 8 nodes/warp

    k_init<<<1, 128>>>(W1, b1, W2, b2, fc_w, fc_b);
    k_deg_acc<<<nb_edges8, TB>>>(ei + E, ew, E);
    k_node<<<nb_warps, TB>>>(x, N);
    k_prop<<<nb_edges8, TB>>>(ei, ew, E);
    k_mid<<<nb_nodes, TB>>>(N);
    k_prop<<<nb_edges8, TB>>>(ei, ew, E);
    k_out<<<nb_nodes, TB>>>(out, N);
}